// round 1
// baseline (speedup 1.0000x reference)
#include <cuda_runtime.h>
#include <math.h>

// Problem constants
#define BB 2
#define HH 240
#define WW 1216
#define CHN 27          // guide channels
#define OC 81           // conv output channels = 3*CHN
#define OCP 88          // padded oc stride for wT
#define HWSZ (HH*WW)            // 291840
#define NPIX (BB*HWSZ)          // 583680
#define KTOT 243

// Scratch (static device globals; no allocation at runtime)
__device__ float g_conv[(size_t)OC * NPIX];                 // raw conv output, plane-major [oc][b][y][x]
__device__ __align__(16) float g_wT[KTOT * OCP];            // transposed padded weights [k][oc]

// ---------- packed fp32x2 helpers ----------
__device__ __forceinline__ unsigned long long pack2(float lo, float hi) {
    unsigned long long r;
    asm("mov.b64 %0, {%1, %2};" : "=l"(r) : "r"(__float_as_uint(lo)), "r"(__float_as_uint(hi)));
    return r;
}
__device__ __forceinline__ unsigned long long packdup(float v) {
    unsigned long long r;
    unsigned u = __float_as_uint(v);
    asm("mov.b64 %0, {%1, %1};" : "=l"(r) : "r"(u));
    return r;
}
__device__ __forceinline__ float2 unpack2(unsigned long long v) {
    unsigned lo, hi;
    asm("mov.b64 {%0, %1}, %2;" : "=r"(lo), "=r"(hi) : "l"(v));
    return make_float2(__uint_as_float(lo), __uint_as_float(hi));
}
#define FMA2(accv, av, bv) asm("fma.rn.f32x2 %0, %1, %2, %0;" : "+l"(accv) : "l"(av), "l"(bv))

// ---------- weight transpose: conv_w [oc][c][ky][kx] -> g_wT [k][ocP], k=(ky*27+c)*3+kx ----------
__global__ void wtrans_kernel(const float* __restrict__ conv_w) {
    int idx = blockIdx.x * 256 + threadIdx.x;
    if (idx < OC * KTOT) {
        int oc = idx / KTOT;
        int r  = idx % KTOT;
        int c  = r / 9;
        int ky = (r % 9) / 3;
        int kx = r % 3;
        int k  = (ky * CHN + c) * 3 + kx;
        g_wT[k * OCP + oc] = conv_w[idx];
    }
    if (idx < KTOT * (OCP - OC)) {   // zero-pad oc 81..87
        int k  = idx / (OCP - OC);
        int oc = OC + idx % (OCP - OC);
        g_wT[k * OCP + oc] = 0.f;
    }
}

// ---------- conv kernel: 128-pixel row tile, all 81 oc, f32x2 over channel pairs ----------
#define TB 352          // 11 warps; warp og covers oc [og*8, og*8+8)
#define PSTR 132        // patch row stride (floats)

__global__ __launch_bounds__(TB) void conv_kernel(const float* __restrict__ guide,
                                                  const float* __restrict__ conv_b) {
    __shared__ float patch[CHN * 3 * PSTR];   // [c*3+dy][132], 130 used -> 42768 B

    const int tid  = threadIdx.x;
    const int lane = tid & 31;
    const int og   = tid >> 5;          // 0..10
    const int x0   = blockIdx.x * 128;
    const int y    = blockIdx.y;
    const int b    = blockIdx.z;

    // stage guide patch with zero padding
    for (int i = tid; i < CHN * 3 * 130; i += TB) {
        int row = i / 130;              // c*3+dy
        int xx  = i % 130;
        int c   = row / 3;
        int dy  = row % 3;
        int yg  = y + dy - 1;
        int xg  = x0 + xx - 1;
        float v = 0.f;
        if (yg >= 0 && yg < HH && xg >= 0 && xg < WW)
            v = guide[((size_t)(b * CHN + c) * HH + yg) * WW + xg];
        patch[row * PSTR + xx] = v;
    }
    __syncthreads();

    const int ocb = og * 8;

    // bias-initialized accumulators: 4 pixels (lane + 32j) x 4 oc-pairs
    unsigned long long acc[4][4];
    {
        float bb[8];
        #pragma unroll
        for (int m = 0; m < 8; m++) bb[m] = (ocb + m < OC) ? conv_b[ocb + m] : 0.f;
        #pragma unroll
        for (int m = 0; m < 4; m++) {
            unsigned long long bp = pack2(bb[2 * m], bb[2 * m + 1]);
            #pragma unroll
            for (int j = 0; j < 4; j++) acc[j][m] = bp;
        }
    }

    // main K loop: k = (dy*27 + c)*3 + kx
    for (int dy = 0; dy < 3; dy++) {
        for (int c = 0; c < CHN; c++) {
            const float* prow = patch + (c * 3 + dy) * PSTR + lane;
            const float* wbase = g_wT + (size_t)((dy * CHN + c) * 3) * OCP + ocb;
            #pragma unroll
            for (int kx = 0; kx < 3; kx++) {
                unsigned long long gg[4];
                #pragma unroll
                for (int j = 0; j < 4; j++) gg[j] = packdup(prow[32 * j + kx]);

                const float4* wp = (const float4*)(wbase + kx * OCP);
                float4 wa = __ldg(wp);
                float4 wb = __ldg(wp + 1);
                unsigned long long w0 = pack2(wa.x, wa.y);
                unsigned long long w1 = pack2(wa.z, wa.w);
                unsigned long long w2 = pack2(wb.x, wb.y);
                unsigned long long w3 = pack2(wb.z, wb.w);

                #pragma unroll
                for (int j = 0; j < 4; j++) {
                    FMA2(acc[j][0], gg[j], w0);
                    FMA2(acc[j][1], gg[j], w1);
                    FMA2(acc[j][2], gg[j], w2);
                    FMA2(acc[j][3], gg[j], w3);
                }
            }
        }
    }

    // epilogue: plane-major stores
    #pragma unroll
    for (int m = 0; m < 4; m++) {
        int oc0 = ocb + 2 * m;
        int oc1 = oc0 + 1;
        #pragma unroll
        for (int j = 0; j < 4; j++) {
            float2 v = unpack2(acc[j][m]);
            int x = x0 + lane + 32 * j;
            if (x < WW) {
                size_t pix = (size_t)b * HWSZ + (size_t)y * WW + x;
                if (oc0 < OC) g_conv[(size_t)oc0 * NPIX + pix] = v.x;
                if (oc1 < OC) g_conv[(size_t)oc1 * NPIX + pix] = v.y;
            }
        }
    }
}

// ---------- propagation: softmax + bilinear-zeros sampling + confidence blend ----------
__global__ void prop_kernel(const float* __restrict__ prev,      // current image, B*HW
                            const float* __restrict__ sp_dep,
                            const float* __restrict__ confid,
                            const float* __restrict__ tap,       // [9][2] (x,y)
                            float* __restrict__ out_cur,         // inter[i]
                            float* __restrict__ pred_out,        // nullable
                            const float* __restrict__ feat_src,  // nullable (iter 0)
                            float* __restrict__ feat_dst,
                            int iter) {
    int p = blockIdx.x * blockDim.x + threadIdx.x;
    if (p >= NPIX) return;
    int b   = p / HWSZ;
    int rem = p % HWSZ;
    int y   = rem / WW;
    int x   = rem % WW;
    const float* img = prev + (size_t)b * HWSZ;

    // raw affinity -> softmax weights
    float araw[9];
    #pragma unroll
    for (int t = 0; t < 9; t++)
        araw[t] = g_conv[(size_t)(2 * OC / 3 + iter * 9 + t) * NPIX + p];  // ch 54 + iter*9 + t
    float mx = araw[0];
    #pragma unroll
    for (int t = 1; t < 9; t++) mx = fmaxf(mx, araw[t]);
    float wv[9];
    float s = 0.f;
    #pragma unroll
    for (int t = 0; t < 9; t++) { wv[t] = expf(araw[t] - mx); s += wv[t]; }
    float inv = 1.f / s;

    float agg = 0.f;
    #pragma unroll
    for (int t = 0; t < 9; t++) {
        float ox = g_conv[(size_t)((iter * 9 + t) * 2)     * NPIX + p];
        float oy = g_conv[(size_t)((iter * 9 + t) * 2 + 1) * NPIX + p];
        float px = ox + tap[2 * t]     + (float)x;
        float py = oy + tap[2 * t + 1] + (float)y;
        float x0f = floorf(px), y0f = floorf(py);
        int xi = (int)x0f, yi = (int)y0f;
        float wx = px - x0f, wy = py - y0f;

        float v00 = 0.f, v01 = 0.f, v10 = 0.f, v11 = 0.f;
        bool xa = (xi >= 0) & (xi < WW);
        bool xb = (xi + 1 >= 0) & (xi + 1 < WW);
        bool ya = (yi >= 0) & (yi < HH);
        bool yb = (yi + 1 >= 0) & (yi + 1 < HH);
        if (ya) {
            const float* r0 = img + (size_t)yi * WW;
            if (xa) v00 = r0[xi];
            if (xb) v01 = r0[xi + 1];
        }
        if (yb) {
            const float* r1 = img + (size_t)(yi + 1) * WW;
            if (xa) v10 = r1[xi];
            if (xb) v11 = r1[xi + 1];
        }
        float v = (1.f - wy) * ((1.f - wx) * v00 + wx * v01)
                +        wy  * ((1.f - wx) * v10 + wx * v11);
        agg += wv[t] * v;
    }
    agg *= inv;

    float sp = sp_dep[p];
    float cf = 1.f / (1.f + expf(-confid[p]));
    float sg = (sp > 0.f) ? 1.f : ((sp < 0.f) ? -1.f : 0.f);
    cf *= sg;
    float o = (1.f - cf) * agg + cf * sp;

    out_cur[p] = o;
    if (pred_out) pred_out[p] = o;
    if (feat_dst) feat_dst[p] = feat_src[p];
}

extern "C" void kernel_launch(void* const* d_in, const int* in_sizes, int n_in,
                              void* d_out, int out_size) {
    const float* input  = (const float*)d_in[0];   // (B,1,H,W)
    const float* guide  = (const float*)d_in[1];   // (B,27,H,W)
    const float* sp_dep = (const float*)d_in[2];   // (B,1,H,W)
    const float* confid = (const float*)d_in[3];   // (B,1,H,W)
    const float* conv_w = (const float*)d_in[4];   // (81,27,3,3)
    const float* conv_b = (const float*)d_in[5];   // (81,)
    const float* tap    = (const float*)d_in[6];   // (9,2)

    float* out   = (float*)d_out;
    float* pred  = out;                 // [0, NPIX)
    float* feat  = out + NPIX;          // [NPIX, 2*NPIX)
    float* inter = out + 2 * (size_t)NPIX;  // 3 slices of NPIX

    // 1. weight transpose
    wtrans_kernel<<<(OC * KTOT + 255) / 256, 256>>>(conv_w);

    // 2. conv (raw outputs -> g_conv planes)
    dim3 cgrid((WW + 127) / 128, HH, BB);
    conv_kernel<<<cgrid, TB>>>(guide, conv_b);

    // 3. propagation chain (inter slices double as cur buffers)
    int pb = (NPIX + 255) / 256;
    prop_kernel<<<pb, 256>>>(input,            sp_dep, confid, tap, inter,            nullptr, input,  feat,    0);
    prop_kernel<<<pb, 256>>>(inter,            sp_dep, confid, tap, inter + NPIX,     nullptr, nullptr, nullptr, 1);
    prop_kernel<<<pb, 256>>>(inter + NPIX,     sp_dep, confid, tap, inter + 2 * (size_t)NPIX, pred, nullptr, nullptr, 2);
}